// round 12
// baseline (speedup 1.0000x reference)
#include <cuda_runtime.h>
#include <math.h>

typedef unsigned long long ull;

namespace {
constexpr int NSEQ = 512;
constexpr int LRES = 1024;
constexpr int NT   = 512;
constexpr float LN_EPS = 1e-5f;

struct __align__(16) Smem {
    float xg[64 * NSEQ];      // 128 KB: X transposed+swizzled, then G in place
    float wpad[64 * 128];     // 32 KB: dup Wg (pass A) -> dup ovec*Wo (pass B), slot-swizzled
    float wkvd[64 * 32];      // 8 KB: dup Wk/Wv as ull[64][16]
    float kT[8 * NSEQ];       // 16 KB: k transposed; later scores[8][512]
    float vT[8 * NSEQ];       // 16 KB
    float lnw[64], lnb[64], bgv[64], bov[64], xsum[64], qvec[64], ovec[64];
    float xpart[16 * 64];     // 4 KB
    float mpart[16], spart[16], opart[16][8];
};  // ~211 KB

__device__ __forceinline__ int swz(int c) { return ((c >> 3) ^ c) & 7; }
__device__ __forceinline__ void ffma2(ull& d_, ull a, ull b) {
    asm("fma.rn.f32x2 %0, %1, %2, %0;" : "+l"(d_) : "l"(a), "l"(b));
}
__device__ __forceinline__ ull splat2(float x) {
    ull r; asm("mov.b64 %0, {%1, %1};" : "=l"(r) : "f"(x)); return r;
}
__device__ __forceinline__ ull add2(ull a, ull b) {
    ull r; asm("add.rn.f32x2 %0, %1, %2;" : "=l"(r) : "l"(a), "l"(b)); return r;
}
__device__ __forceinline__ void unpack2(ull u, float& lo, float& hi) {
    asm("mov.b64 {%0, %1}, %2;" : "=f"(lo), "=f"(hi) : "l"(u));
}
// sigmoid(x) = 0.5*tanh(x/2) + 0.5  (single MUFU)
__device__ __forceinline__ float sigmoid_t(float v) {
    float t; asm("tanh.approx.f32 %0, %1;" : "=f"(t) : "f"(v * 0.5f));
    return fmaf(t, 0.5f, 0.5f);
}
} // namespace

__global__ void __launch_bounds__(NT, 1)
msa_col_attn_v12(const float* __restrict__ msa,
                 const float* __restrict__ g_lnw, const float* __restrict__ g_lnb,
                 const float* __restrict__ g_wq,  const float* __restrict__ g_wk,
                 const float* __restrict__ g_wv,  const float* __restrict__ g_wg,
                 const float* __restrict__ g_bg,  const float* __restrict__ g_wo,
                 const float* __restrict__ g_bo,  float* __restrict__ out)
{
    extern __shared__ float smf[];
    Smem* s = reinterpret_cast<Smem*>(smf);
    const int tid  = threadIdx.x;
    const int l    = blockIdx.x;
    const int lane = tid & 31;
    const int wid  = tid >> 5;

    const int rg  = tid >> 3;       // rows 8rg..8rg+7
    const int cg  = tid & 7;        // cols 8cg..8cg+7
    const int cg2 = cg >> 1;

    // ---------------- preamble: duplicated weights to SMEM ----------------
    {
        // Wg dup, slot-swizzled: thread (d = tid>>3, cgp = tid&7) handles cols 8cgp..+7 of row d
        int d = tid >> 3, cgp = tid & 7, cp2 = cgp >> 1;
        float4 wA = *reinterpret_cast<const float4*>(g_wg + d * 64 + 8 * cgp);
        float4 wB = *reinterpret_cast<const float4*>(g_wg + d * 64 + 8 * cgp + 4);
        float wv8[8] = {wA.x, wA.y, wA.z, wA.w, wB.x, wB.y, wB.z, wB.w};
        #pragma unroll
        for (int i = 0; i < 4; ++i) {
            int slot = cgp * 4 + ((i + cp2) & 3);
            *reinterpret_cast<float4*>(s->wpad + d * 128 + slot * 4) =
                make_float4(wv8[2*i], wv8[2*i], wv8[2*i+1], wv8[2*i+1]);
        }
        // Wk/Wv dup: ull[64][16], cols 0-7 = k, 8-15 = v
        int j = tid & 7;
        ull* kvd = reinterpret_cast<ull*>(s->wkvd);
        kvd[d * 16 + j]     = splat2(g_wk[tid]);
        kvd[d * 16 + 8 + j] = splat2(g_wv[tid]);
        if (tid < 64) {
            s->lnw[tid] = g_lnw[tid];
            s->lnb[tid] = g_lnb[tid];
            s->bgv[tid] = g_bg[tid];
            s->bov[tid] = g_bo[tid];
        }
    }
    // wq in registers
    float wqr[8];
    {
        int dg = tid >> 6, c = tid & 63;
        #pragma unroll
        for (int i = 0; i < 8; ++i) wqr[i] = g_wq[(8 * dg + i) * 64 + c];
    }
    __syncthreads();

    // ---------------- LayerNorm: 512x64 -> xg transposed+swizzled (prefetch 4) ----------------
    {
        const int lq4 = lane & 15;
        const int lh  = lane >> 4;
        const size_t step = (size_t)32 * LRES * 64;
        const float* base = msa + ((size_t)(wid * 2 + lh) * LRES + l) * 64 + lq4 * 4;
        float xacc0 = 0.f, xacc1 = 0.f, xacc2 = 0.f, xacc3 = 0.f;
        float4 buf[4];
        #pragma unroll
        for (int j = 0; j < 4; ++j)
            buf[j] = *reinterpret_cast<const float4*>(base + (size_t)j * step);
        #pragma unroll 4
        for (int it = 0; it < 16; ++it) {
            float4 cur = buf[it & 3];
            if (it + 4 < 16)
                buf[it & 3] = *reinterpret_cast<const float4*>(base + (size_t)(it + 4) * step);
            float sm = (cur.x + cur.y) + (cur.z + cur.w);
            float sq = fmaf(cur.x, cur.x, fmaf(cur.y, cur.y,
                       fmaf(cur.z, cur.z, cur.w * cur.w)));
            #pragma unroll
            for (int off = 1; off < 16; off <<= 1) {
                sm += __shfl_xor_sync(0xffffffffu, sm, off);
                sq += __shfl_xor_sync(0xffffffffu, sq, off);
            }
            float mu   = sm * (1.f / 64.f);
            float var  = sq * (1.f / 64.f) - mu * mu;
            float rstd = rsqrtf(var + LN_EPS);
            float mrs  = -mu * rstd;
            int row = it * 32 + wid * 2 + lh;
            int rb = row >> 2, r0 = row & 3;
            int c0 = 4 * lq4;
            float v0 = fmaf(fmaf(cur.x, rstd, mrs), s->lnw[c0 + 0], s->lnb[c0 + 0]);
            float v1 = fmaf(fmaf(cur.y, rstd, mrs), s->lnw[c0 + 1], s->lnb[c0 + 1]);
            float v2 = fmaf(fmaf(cur.z, rstd, mrs), s->lnw[c0 + 2], s->lnb[c0 + 2]);
            float v3 = fmaf(fmaf(cur.w, rstd, mrs), s->lnw[c0 + 3], s->lnb[c0 + 3]);
            s->xg[(c0 + 0) * NSEQ + 4 * (rb ^ swz(c0 + 0)) + r0] = v0;
            s->xg[(c0 + 1) * NSEQ + 4 * (rb ^ swz(c0 + 1)) + r0] = v1;
            s->xg[(c0 + 2) * NSEQ + 4 * (rb ^ swz(c0 + 2)) + r0] = v2;
            s->xg[(c0 + 3) * NSEQ + 4 * (rb ^ swz(c0 + 3)) + r0] = v3;
            xacc0 += v0; xacc1 += v1; xacc2 += v2; xacc3 += v3;
        }
        xacc0 += __shfl_xor_sync(0xffffffffu, xacc0, 16);
        xacc1 += __shfl_xor_sync(0xffffffffu, xacc1, 16);
        xacc2 += __shfl_xor_sync(0xffffffffu, xacc2, 16);
        xacc3 += __shfl_xor_sync(0xffffffffu, xacc3, 16);
        if (lane < 16) {
            float* xp = s->xpart + wid * 64 + 4 * lq4;
            xp[0] = xacc0; xp[1] = xacc1; xp[2] = xacc2; xp[3] = xacc3;
        }
    }
    __syncthreads();

    // xsum (consumed after next barrier)
    if (tid < 64) {
        float t = 0.f;
        #pragma unroll
        for (int w = 0; w < 16; ++w) t += s->xpart[w * 64 + tid];
        s->xsum[tid] = t;
    }

    // precomputed swizzled weight base pointers (chunk i covers cols 8cg+2i,+1)
    const float* wg0 = s->wpad + cg * 16 + (((0) + cg2) & 3) * 4;
    const float* wg1 = s->wpad + cg * 16 + (((1) + cg2) & 3) * 4;
    const float* wg2 = s->wpad + cg * 16 + (((2) + cg2) & 3) * 4;
    const float* wg3 = s->wpad + cg * 16 + (((3) + cg2) & 3) * 4;
    const ull*   kvb = reinterpret_cast<const ull*>(s->wkvd) + 2 * cg;
    const int r2a = 2 * rg, r2b = 2 * rg + 1;

    // ---------------- pass A: fused gate + kv GEMM (x row-pair packed, zero splats) ----------------
    ull ga[4][8];     // [rowpair][col]
    ull ka[4][2];     // [rowpair][kv col pair]
    #pragma unroll
    for (int p = 0; p < 4; ++p) {
        ka[p][0] = 0; ka[p][1] = 0;
        #pragma unroll
        for (int c = 0; c < 8; ++c) ga[p][c] = 0;
    }
    #pragma unroll 1
    for (int a = 0; a < 8; ++a) {
        const float* xcol = s->xg + a * 8 * NSEQ;
        const int ea = (r2a ^ a) << 2;
        const int eb = (r2b ^ a) << 2;
        #pragma unroll
        for (int b = 0; b < 8; ++b) {
            const float* xc = xcol + b * NSEQ;
            ulonglong2 xa = *reinterpret_cast<const ulonglong2*>(xc + (ea ^ (b << 2)));
            ulonglong2 xb = *reinterpret_cast<const ulonglong2*>(xc + (eb ^ (b << 2)));
            const int doff = (a * 8 + b) * 128;
            ulonglong2 w0 = *reinterpret_cast<const ulonglong2*>(wg0 + doff);
            ulonglong2 w1 = *reinterpret_cast<const ulonglong2*>(wg1 + doff);
            ulonglong2 w2 = *reinterpret_cast<const ulonglong2*>(wg2 + doff);
            ulonglong2 w3 = *reinterpret_cast<const ulonglong2*>(wg3 + doff);
            ulonglong2 wk = *reinterpret_cast<const ulonglong2*>(kvb + (a * 8 + b) * 16);
            #define ROWA(rp, xp) \
                ffma2(ga[rp][0], xp, w0.x); ffma2(ga[rp][1], xp, w0.y); \
                ffma2(ga[rp][2], xp, w1.x); ffma2(ga[rp][3], xp, w1.y); \
                ffma2(ga[rp][4], xp, w2.x); ffma2(ga[rp][5], xp, w2.y); \
                ffma2(ga[rp][6], xp, w3.x); ffma2(ga[rp][7], xp, w3.y); \
                ffma2(ka[rp][0], xp, wk.x); ffma2(ka[rp][1], xp, wk.y);
            ROWA(0, xa.x) ROWA(1, xa.y) ROWA(2, xb.x) ROWA(3, xb.y)
            #undef ROWA
        }
    }
    __syncthreads();   // all xg reads done; safe to overwrite with G

    // gate epilogue: G = sigmoid(P + bg) -> xg (ull holds row pair -> unpack gives col's rows)
    #pragma unroll
    for (int c = 0; c < 8; ++c) {
        int col = 8 * cg + c;
        float bgc = s->bgv[col];
        float g[8];
        unpack2(ga[0][c], g[0], g[1]);
        unpack2(ga[1][c], g[2], g[3]);
        unpack2(ga[2][c], g[4], g[5]);
        unpack2(ga[3][c], g[6], g[7]);
        #pragma unroll
        for (int r = 0; r < 8; ++r) g[r] = sigmoid_t(g[r] + bgc);
        float* dst = &s->xg[col * NSEQ];
        *reinterpret_cast<float4*>(dst + 4 * (r2a ^ swz(col))) = make_float4(g[0], g[1], g[2], g[3]);
        *reinterpret_cast<float4*>(dst + 4 * (r2b ^ swz(col))) = make_float4(g[4], g[5], g[6], g[7]);
    }
    // kv epilogue -> kT / vT (both transposed)
    #pragma unroll
    for (int c = 0; c < 2; ++c) {
        int gcol = 2 * cg + c;       // 0-7 = k col, 8-15 = v col
        float k8[8];
        unpack2(ka[0][c], k8[0], k8[1]);
        unpack2(ka[1][c], k8[2], k8[3]);
        unpack2(ka[2][c], k8[4], k8[5]);
        unpack2(ka[3][c], k8[6], k8[7]);
        float* dst = (gcol < 8) ? (s->kT + gcol * NSEQ) : (s->vT + (gcol - 8) * NSEQ);
        *reinterpret_cast<float4*>(dst + 8 * rg)     = make_float4(k8[0], k8[1], k8[2], k8[3]);
        *reinterpret_cast<float4*>(dst + 8 * rg + 4) = make_float4(k8[4], k8[5], k8[6], k8[7]);
    }
    // qvec partials (xsum written before previous barrier)
    {
        int dg = tid >> 6, c = tid & 63;
        float p = 0.f;
        #pragma unroll
        for (int i = 0; i < 8; ++i) p = fmaf(s->xsum[8 * dg + i], wqr[i], p);
        s->xpart[dg * 64 + c] = p;
    }
    __syncthreads();

    // qvec reduce; every thread stashes its k column in regs (kT overlaid by scores next)
    if (tid < 64) {
        float q = 0.f;
        #pragma unroll
        for (int dg = 0; dg < 8; ++dg) q += s->xpart[dg * 64 + tid];
        s->qvec[tid] = q * (float)(0.35355339059327373 / 512.0); // (1/sqrt(8))/N
    }
    float kk[8];
    #pragma unroll
    for (int d = 0; d < 8; ++d) kk[d] = s->kT[d * NSEQ + tid];
    __syncthreads();

    // ---------------- scores[h][n] (overlay kT) ----------------
    {
        float* scores = s->kT;
        #pragma unroll
        for (int h = 0; h < 8; ++h) {
            const float* qf = &s->qvec[h * 8];
            float sc = qf[0]*kk[0] + qf[1]*kk[1] + qf[2]*kk[2] + qf[3]*kk[3]
                     + qf[4]*kk[4] + qf[5]*kk[5] + qf[6]*kk[6] + qf[7]*kk[7];
            scores[h * NSEQ + tid] = sc;
        }
    }
    __syncthreads();

    // ---------------- softmax partials: 2 warps per head ----------------
    {
        int h = wid >> 1, half = wid & 1;
        const float* sc = s->kT + h * NSEQ + half * 256;
        float sv[8], m = -1e30f;
        #pragma unroll
        for (int k = 0; k < 8; ++k) { sv[k] = sc[lane + 32 * k]; m = fmaxf(m, sv[k]); }
        #pragma unroll
        for (int off = 16; off > 0; off >>= 1)
            m = fmaxf(m, __shfl_xor_sync(0xffffffffu, m, off));
        float ssum = 0.f, acc[8];
        #pragma unroll
        for (int d = 0; d < 8; ++d) acc[d] = 0.f;
        #pragma unroll
        for (int k = 0; k < 8; ++k) {
            float e = __expf(sv[k] - m);
            ssum += e;
            int n = half * 256 + lane + 32 * k;
            #pragma unroll
            for (int d = 0; d < 8; ++d) acc[d] = fmaf(e, s->vT[d * NSEQ + n], acc[d]);
        }
        #pragma unroll
        for (int off = 16; off > 0; off >>= 1) {
            ssum += __shfl_xor_sync(0xffffffffu, ssum, off);
            #pragma unroll
            for (int d = 0; d < 8; ++d) acc[d] += __shfl_xor_sync(0xffffffffu, acc[d], off);
        }
        if (lane == 0) {
            s->mpart[wid] = m;
            s->spart[wid] = ssum;
            #pragma unroll
            for (int d = 0; d < 8; ++d) s->opart[wid][d] = acc[d];
        }
    }
    __syncthreads();

    // ovec combine (exact two-way softmax merge)
    if (tid < 64) {
        int h = tid >> 3, d = tid & 7;
        float m0 = s->mpart[2 * h], m1 = s->mpart[2 * h + 1];
        float m = fmaxf(m0, m1);
        float e0 = __expf(m0 - m), e1 = __expf(m1 - m);
        float ss = s->spart[2 * h] * e0 + s->spart[2 * h + 1] * e1;
        float ov = s->opart[2 * h][d] * e0 + s->opart[2 * h + 1][d] * e1;
        s->ovec[8 * h + d] = ov / ss;
    }
    __syncthreads();

    // ---------------- fold ovec into dup Wo -> wpad (wgd dead) ----------------
    {
        int d = tid >> 3, cgp = tid & 7, cp2 = cgp >> 1;
        float ov = s->ovec[d];
        float4 wA = *reinterpret_cast<const float4*>(g_wo + d * 64 + 8 * cgp);
        float4 wB = *reinterpret_cast<const float4*>(g_wo + d * 64 + 8 * cgp + 4);
        float wv8[8] = {wA.x * ov, wA.y * ov, wA.z * ov, wA.w * ov,
                        wB.x * ov, wB.y * ov, wB.z * ov, wB.w * ov};
        #pragma unroll
        for (int i = 0; i < 4; ++i) {
            int slot = cgp * 4 + ((i + cp2) & 3);
            *reinterpret_cast<float4*>(s->wpad + d * 128 + slot * 4) =
                make_float4(wv8[2*i], wv8[2*i], wv8[2*i+1], wv8[2*i+1]);
        }
    }
    __syncthreads();

    // ---------------- pass B: out = G @ Wo' + bo ----------------
    {
        ull acc[4][8];
        #pragma unroll
        for (int p = 0; p < 4; ++p)
            #pragma unroll
            for (int c = 0; c < 8; ++c) acc[p][c] = 0;

        #pragma unroll 1
        for (int a = 0; a < 8; ++a) {
            const float* gcol = s->xg + a * 8 * NSEQ;
            const int ea = (r2a ^ a) << 2;
            const int eb = (r2b ^ a) << 2;
            #pragma unroll
            for (int b = 0; b < 8; ++b) {
                const float* xc = gcol + b * NSEQ;
                ulonglong2 xa = *reinterpret_cast<const ulonglong2*>(xc + (ea ^ (b << 2)));
                ulonglong2 xb = *reinterpret_cast<const ulonglong2*>(xc + (eb ^ (b << 2)));
                const int doff = (a * 8 + b) * 128;
                ulonglong2 w0 = *reinterpret_cast<const ulonglong2*>(wg0 + doff);
                ulonglong2 w1 = *reinterpret_cast<const ulonglong2*>(wg1 + doff);
                ulonglong2 w2 = *reinterpret_cast<const ulonglong2*>(wg2 + doff);
                ulonglong2 w3 = *reinterpret_cast<const ulonglong2*>(wg3 + doff);
                #define ROWB(rp, xp) \
                    ffma2(acc[rp][0], xp, w0.x); ffma2(acc[rp][1], xp, w0.y); \
                    ffma2(acc[rp][2], xp, w1.x); ffma2(acc[rp][3], xp, w1.y); \
                    ffma2(acc[rp][4], xp, w2.x); ffma2(acc[rp][5], xp, w2.y); \
                    ffma2(acc[rp][6], xp, w3.x); ffma2(acc[rp][7], xp, w3.y);
                ROWB(0, xa.x) ROWB(1, xa.y) ROWB(2, xb.x) ROWB(3, xb.y)
                #undef ROWB
            }
        }

        float bo8[8];
        #pragma unroll
        for (int c = 0; c < 8; ++c) bo8[c] = s->bov[8 * cg + c];
        #pragma unroll
        for (int rp = 0; rp < 4; ++rp) {
            float e[8], o[8];
            #pragma unroll
            for (int c = 0; c < 8; ++c) {
                unpack2(acc[rp][c], e[c], o[c]);
                e[c] += bo8[c]; o[c] += bo8[c];
            }
            size_t re = (size_t)(8 * rg + 2 * rp);
            float* ope = out + (re * LRES + l) * 64 + 8 * cg;
            float* opo = ope + (size_t)LRES * 64;
            *reinterpret_cast<float4*>(ope)     = make_float4(e[0], e[1], e[2], e[3]);
            *reinterpret_cast<float4*>(ope + 4) = make_float4(e[4], e[5], e[6], e[7]);
            *reinterpret_cast<float4*>(opo)     = make_float4(o[0], o[1], o[2], o[3]);
            *reinterpret_cast<float4*>(opo + 4) = make_float4(o[4], o[5], o[6], o[7]);
        }
    }
}

extern "C" void kernel_launch(void* const* d_in, const int* in_sizes, int n_in,
                              void* d_out, int out_size) {
    const float* msa = (const float*)d_in[0];
    const float* lnw = (const float*)d_in[1];
    const float* lnb = (const float*)d_in[2];
    const float* wq  = (const float*)d_in[3];
    const float* wk  = (const float*)d_in[4];
    const float* wv  = (const float*)d_in[5];
    const float* wg  = (const float*)d_in[6];
    const float* bg  = (const float*)d_in[7];
    const float* wo  = (const float*)d_in[8];
    const float* bo  = (const float*)d_in[9];
    float* out = (float*)d_out;

    const int smem_bytes = (int)sizeof(Smem);
    cudaFuncSetAttribute(msa_col_attn_v12,
                         cudaFuncAttributeMaxDynamicSharedMemorySize, smem_bytes);
    msa_col_attn_v12<<<LRES, NT, smem_bytes>>>(
        msa, lnw, lnb, wq, wk, wv, wg, bg, wo, bo, out);
}